// round 9
// baseline (speedup 1.0000x reference)
#include <cuda_runtime.h>
#include <cuda_bf16.h>
#include <math.h>
#include <stdint.h>

// Problem dims (fixed)
#define Bb   2048
#define Nn   128
#define Dd   512
#define HIDD 2048
#define Hh   8
#define DHh  64

// ---------------- scratch (device globals; no allocations) ----------------
__device__ __nv_bfloat16 g_cath[Bb * Dd],  g_catl[Bb * Dd];
__device__ __nv_bfloat16 g_H1h[Bb * HIDD], g_H1l[Bb * HIDD];
__device__ __nv_bfloat16 g_H2h[Bb * HIDD], g_H2l[Bb * HIDD];
__device__ __nv_bfloat16 g_embh[Bb * Dd],  g_embl[Bb * Dd];
__device__ __nv_bfloat16 g_qh[Bb * Dd],    g_ql[Bb * Dd];
__device__ __nv_bfloat16 g_ch[Bb * Hh * Dd], g_cl[Bb * Hh * Dd];
__device__ __nv_bfloat16 g_ctxh[Bb * Dd],  g_ctxl[Bb * Dd];
__device__ __nv_bfloat16 g_W1Th[HIDD * Dd], g_W1Tl[HIDD * Dd];
__device__ __nv_bfloat16 g_W2h[HIDD * HIDD], g_W2l[HIDD * HIDD];
__device__ __nv_bfloat16 g_W3Th[Dd * HIDD], g_W3Tl[Dd * HIDD];
__device__ __nv_bfloat16 g_WqTh[Dd * Dd],  g_WqTl[Dd * Dd];
__device__ __nv_bfloat16 g_Wkh[Dd * Dd],   g_Wkl[Dd * Dd];
__device__ __nv_bfloat16 g_WvTh[Dd * Dd],  g_WvTl[Dd * Dd];
__device__ __nv_bfloat16 g_WoTh[Dd * Dd],  g_WoTl[Dd * Dd];
__device__ float g_r[Bb * Hh * Dd];
__device__ float g_bnS[HIDD];
__device__ float g_bnT[HIDD];
__device__ float g_bias2[HIDD];

// ================= helpers =================
__device__ __forceinline__ uint32_t smem_u32(const void* p) {
    uint32_t a;
    asm("{ .reg .u64 t; cvta.to.shared.u64 t, %1; cvt.u32.u64 %0, t; }"
        : "=r"(a) : "l"(p));
    return a;
}
__device__ __forceinline__ void cpasync16(uint32_t dst, const void* src) {
    asm volatile("cp.async.cg.shared.global [%0], [%1], 16;"
                 :: "r"(dst), "l"(src) : "memory");
}
__device__ __forceinline__ void cpcommit() {
    asm volatile("cp.async.commit_group;" ::: "memory");
}
template <int N>
__device__ __forceinline__ void cpwait() {
    asm volatile("cp.async.wait_group %0;" :: "n"(N) : "memory");
}
__device__ __forceinline__ void ldm4(uint32_t* r, uint32_t addr) {
    asm volatile("ldmatrix.sync.aligned.m8n8.x4.shared.b16 {%0,%1,%2,%3}, [%4];"
                 : "=r"(r[0]), "=r"(r[1]), "=r"(r[2]), "=r"(r[3]) : "r"(addr));
}
__device__ __forceinline__ void mma16816(float* c, const uint32_t* a,
                                         const uint32_t* b) {
    asm volatile(
        "mma.sync.aligned.m16n8k16.row.col.f32.bf16.bf16.f32 "
        "{%0,%1,%2,%3}, {%4,%5,%6,%7}, {%8,%9}, {%0,%1,%2,%3};"
        : "+f"(c[0]), "+f"(c[1]), "+f"(c[2]), "+f"(c[3])
        : "r"(a[0]), "r"(a[1]), "r"(a[2]), "r"(a[3]), "r"(b[0]), "r"(b[1]));
}
__device__ __forceinline__ void split_store(float x, float y,
                                            __nv_bfloat16* ph,
                                            __nv_bfloat16* pl) {
    __nv_bfloat162 h = __floats2bfloat162_rn(x, y);
    float rx = x - __bfloat162float(h.x);
    float ry = y - __bfloat162float(h.y);
    __nv_bfloat162 l = __floats2bfloat162_rn(rx, ry);
    *reinterpret_cast<uint32_t*>(ph) = *reinterpret_cast<uint32_t*>(&h);
    *reinterpret_cast<uint32_t*>(pl) = *reinterpret_cast<uint32_t*>(&l);
}
// fast accurate tanh via __expf (err ~1e-7, vs slow libm tanhf path)
__device__ __forceinline__ float ftanh(float x) {
    float e = __expf(-2.f * fabsf(x));
    float r = __fdividef(1.f - e, 1.f + e);
    return copysignf(r, x);
}

// ================= bf16x3 GEMM, TBK=64, 3-stage cp.async, 1 sync/iter ======
template <int TBN, bool DOTANH, int OUTMODE>
__global__ void __launch_bounds__(256)
bgemm(const __nv_bfloat16* __restrict__ Ah, const __nv_bfloat16* __restrict__ Al,
      int lda, long sAz,
      const __nv_bfloat16* __restrict__ Bh, const __nv_bfloat16* __restrict__ Bl,
      int ldb, long sBz,
      float* __restrict__ C, __nv_bfloat16* __restrict__ Ch,
      __nv_bfloat16* __restrict__ Cl, int ldc, long sCz,
      const float* __restrict__ bias, long sBiasz, int K, float scale)
{
    constexpr int TBM = 128, TBK = 64;
    constexpr int WN = TBN / 4;
    constexpr int NF = WN / 8;
    constexpr int STRIDE = 144;
    constexpr int OA_L = TBM * STRIDE;
    constexpr int OB_H = 2 * TBM * STRIDE;
    constexpr int OB_L = OB_H + TBN * STRIDE;
    constexpr int STAGE = OB_H + 2 * TBN * STRIDE;

    extern __shared__ __align__(16) char dynsm[];
    const uint32_t sb0 = smem_u32(dynsm);

    const int tid = threadIdx.x, wid = tid >> 5, lane = tid & 31;
    const int wm = wid >> 2, wn = wid & 3;

    Ah += (size_t)blockIdx.z * sAz + (size_t)blockIdx.y * TBM * lda;
    Al += (size_t)blockIdx.z * sAz + (size_t)blockIdx.y * TBM * lda;
    Bh += (size_t)blockIdx.z * sBz + (size_t)blockIdx.x * TBN * ldb;
    Bl += (size_t)blockIdx.z * sBz + (size_t)blockIdx.x * TBN * ldb;

    const uint32_t aoff = (uint32_t)(wm * 64 + (lane & 15)) * STRIDE
                        + (uint32_t)((lane >> 4) * 8) * 2;
    const uint32_t boff = (uint32_t)(wn * WN + ((lane >> 4) & 1) * 8 + (lane & 7))
                          * STRIDE
                        + (uint32_t)(((lane >> 3) & 1) * 8) * 2;

    float acc[4][NF][4];
#pragma unroll
    for (int i = 0; i < 4; i++)
#pragma unroll
        for (int j = 0; j < NF; j++)
#pragma unroll
            for (int e = 0; e < 4; e++) acc[i][j][e] = 0.f;

    auto issueStage = [&](int kt, int buf) {
        const uint32_t sb = sb0 + buf * STAGE;
        const int k0 = kt * TBK;
#pragma unroll
        for (int i = 0; i < 4; i++) {
            int idx = tid + i * 256;
            int r = idx >> 3, cc = idx & 7;
            const size_t go = (size_t)r * lda + k0 + cc * 8;
            const uint32_t so = (uint32_t)r * STRIDE + cc * 16;
            cpasync16(sb + so, Ah + go);
            cpasync16(sb + OA_L + so, Al + go);
        }
#pragma unroll
        for (int i = 0; i < TBN / 32; i++) {
            int idx = tid + i * 256;
            int r = idx >> 3, cc = idx & 7;
            const size_t go = (size_t)r * ldb + k0 + cc * 8;
            const uint32_t so = (uint32_t)r * STRIDE + cc * 16;
            cpasync16(sb + OB_H + so, Bh + go);
            cpasync16(sb + OB_L + so, Bl + go);
        }
        cpcommit();
    };

    auto compute = [&](int buf) {
        const uint32_t sb = sb0 + buf * STAGE;
#pragma unroll
        for (int kh = 0; kh < 4; ++kh) {
            const uint32_t kb = (uint32_t)kh * 32;
            uint32_t bh[NF][2], bl[NF][2];
#pragma unroll
            for (int p = 0; p < NF / 2; ++p) {
                uint32_t r4[4];
                ldm4(r4, sb + OB_H + boff + p * 16u * STRIDE + kb);
                bh[2 * p][0] = r4[0]; bh[2 * p][1] = r4[1];
                bh[2 * p + 1][0] = r4[2]; bh[2 * p + 1][1] = r4[3];
                ldm4(r4, sb + OB_L + boff + p * 16u * STRIDE + kb);
                bl[2 * p][0] = r4[0]; bl[2 * p][1] = r4[1];
                bl[2 * p + 1][0] = r4[2]; bl[2 * p + 1][1] = r4[3];
            }
#pragma unroll
            for (int mf = 0; mf < 4; ++mf) {
                uint32_t ah[4], al[4];
                ldm4(ah, sb + aoff + (uint32_t)mf * 16u * STRIDE + kb);
                ldm4(al, sb + OA_L + aoff + (uint32_t)mf * 16u * STRIDE + kb);
#pragma unroll
                for (int nf = 0; nf < NF; ++nf) {
                    mma16816(acc[mf][nf], ah, bh[nf]);
                    mma16816(acc[mf][nf], ah, bl[nf]);
                    mma16816(acc[mf][nf], al, bh[nf]);
                }
            }
        }
    };

    const int KT = K / TBK;
    issueStage(0, 0);
    if (KT > 1) issueStage(1, 1);
    for (int kt = 0; kt < KT; ++kt) {
        if (kt + 1 < KT) cpwait<1>(); else cpwait<0>();
        __syncthreads();
        if (kt + 2 < KT) issueStage(kt + 2, (kt + 2) % 3);
        compute(kt % 3);
    }

    const float* bp = bias ? bias + (size_t)blockIdx.z * sBiasz
                           + (size_t)blockIdx.x * TBN
                         : nullptr;
    const size_t cbase = (size_t)blockIdx.z * sCz
                       + (size_t)blockIdx.y * TBM * ldc
                       + (size_t)blockIdx.x * TBN;
    const int r1 = lane >> 2, c1 = (lane & 3) * 2;
#pragma unroll
    for (int mf = 0; mf < 4; ++mf) {
#pragma unroll
        for (int nf = 0; nf < NF; ++nf) {
            int col = wn * WN + nf * 8 + c1;
            float bx = bp ? bp[col] : 0.f, by = bp ? bp[col + 1] : 0.f;
            int row0 = wm * 64 + mf * 16 + r1;
            float2 v0, v1;
            v0.x = acc[mf][nf][0] * scale + bx;
            v0.y = acc[mf][nf][1] * scale + by;
            v1.x = acc[mf][nf][2] * scale + bx;
            v1.y = acc[mf][nf][3] * scale + by;
            if (DOTANH) {
                v0.x = ftanh(v0.x); v0.y = ftanh(v0.y);
                v1.x = ftanh(v1.x); v1.y = ftanh(v1.y);
            }
            size_t o0 = cbase + (size_t)row0 * ldc + col;
            size_t o1 = cbase + (size_t)(row0 + 8) * ldc + col;
            if (OUTMODE == 0) {
                *(float2*)(C + o0) = v0;
                *(float2*)(C + o1) = v1;
            } else {
                split_store(v0.x, v0.y, Ch + o0, Cl + o0);
                split_store(v1.x, v1.y, Ch + o1, Cl + o1);
            }
        }
    }
}

// ---------------- weight prep kernels ----------------
__global__ void transposeSplit(const float* __restrict__ in,
                               __nv_bfloat16* __restrict__ oh,
                               __nv_bfloat16* __restrict__ ol, int R, int C)
{
    __shared__ float t[32][33];
    int bx = blockIdx.x * 32, by = blockIdx.y * 32;
    int x = threadIdx.x, y = threadIdx.y;
#pragma unroll
    for (int i = 0; i < 32; i += 8)
        t[y + i][x] = in[(size_t)(by + y + i) * C + bx + x];
    __syncthreads();
#pragma unroll
    for (int i = 0; i < 32; i += 8) {
        float v = t[x][y + i];
        __nv_bfloat16 h = __float2bfloat16(v);
        size_t o = (size_t)(bx + y + i) * R + by + x;
        oh[o] = h;
        ol[o] = __float2bfloat16(v - __bfloat162float(h));
    }
}
__global__ void transposeSplit512x3(
    const float* __restrict__ s0, const float* __restrict__ s1,
    const float* __restrict__ s2,
    __nv_bfloat16* __restrict__ h0, __nv_bfloat16* __restrict__ l0,
    __nv_bfloat16* __restrict__ h1, __nv_bfloat16* __restrict__ l1,
    __nv_bfloat16* __restrict__ h2, __nv_bfloat16* __restrict__ l2)
{
    const float* in = blockIdx.z == 0 ? s0 : blockIdx.z == 1 ? s1 : s2;
    __nv_bfloat16* oh = blockIdx.z == 0 ? h0 : blockIdx.z == 1 ? h1 : h2;
    __nv_bfloat16* ol = blockIdx.z == 0 ? l0 : blockIdx.z == 1 ? l1 : l2;
    __shared__ float t[32][33];
    int bx = blockIdx.x * 32, by = blockIdx.y * 32;
    int x = threadIdx.x, y = threadIdx.y;
#pragma unroll
    for (int i = 0; i < 32; i += 8)
        t[y + i][x] = in[(size_t)(by + y + i) * 512 + bx + x];
    __syncthreads();
#pragma unroll
    for (int i = 0; i < 32; i += 8) {
        float v = t[x][y + i];
        __nv_bfloat16 h = __float2bfloat16(v);
        size_t o = (size_t)(bx + y + i) * 512 + by + x;
        oh[o] = h;
        ol[o] = __float2bfloat16(v - __bfloat162float(h));
    }
}
__global__ void splitOnly(const float* __restrict__ in,
                          __nv_bfloat16* __restrict__ oh,
                          __nv_bfloat16* __restrict__ ol, int n4)
{
    int i = blockIdx.x * blockDim.x + threadIdx.x;
    if (i >= n4) return;
    float4 v = ((const float4*)in)[i];
    split_store(v.x, v.y, oh + (size_t)i * 4, ol + (size_t)i * 4);
    split_store(v.z, v.w, oh + (size_t)i * 4 + 2, ol + (size_t)i * 4 + 2);
}

// ---------------- BatchNorm stats (also inits bias2 = b2) ----------------
__global__ void bn_stats_kernel(const __nv_bfloat16* __restrict__ H1h,
                                const __nv_bfloat16* __restrict__ H1l,
                                const float* __restrict__ gamma,
                                const float* __restrict__ beta,
                                const float* __restrict__ b2,
                                float* __restrict__ S, float* __restrict__ T,
                                float* __restrict__ bias2)
{
    __shared__ float ss[16][16], sq[16][16];
    const int col0 = blockIdx.x * 16;
    const int c = threadIdx.x & 15, rg = threadIdx.x >> 4;
    float s = 0.f, q = 0.f;
#pragma unroll 4
    for (int i = 0; i < 128; ++i) {
        size_t idx = (size_t)(rg * 128 + i) * HIDD + col0 + c;
        float v = __bfloat162float(H1h[idx]) + __bfloat162float(H1l[idx]);
        s += v;
        q += v * v;
    }
    ss[rg][c] = s;
    sq[rg][c] = q;
    __syncthreads();
    if (threadIdx.x < 16) {
        float st = 0.f, qt = 0.f;
#pragma unroll
        for (int g = 0; g < 16; ++g) { st += ss[g][threadIdx.x]; qt += sq[g][threadIdx.x]; }
        float mu = st / 2048.f;
        float var = qt / 2048.f - mu * mu;
        float rstd = rsqrtf(var + 1e-5f);
        float sc = gamma[col0 + threadIdx.x] * rstd;
        S[col0 + threadIdx.x] = sc;
        T[col0 + threadIdx.x] = beta[col0 + threadIdx.x] - mu * sc;
        bias2[col0 + threadIdx.x] = b2[col0 + threadIdx.x];
    }
}

// ---------------- fused W2 prep: read W2 directly ----------------
// W2hat[n][k] = S[k] * W2[k][n] (transposed, split bf16);
// bias2[n] += sum_k T[k] * W2[k][n] (per-tile partials + atomicAdd).
__global__ void w2prepFused(const float* __restrict__ W2,
                            const float* __restrict__ S,
                            const float* __restrict__ T,
                            __nv_bfloat16* __restrict__ W2h,
                            __nv_bfloat16* __restrict__ W2l,
                            float* __restrict__ bias2)
{
    __shared__ float t[32][33];
    __shared__ float red[8][33];
    const int n0 = blockIdx.x * 32, k0 = blockIdx.y * 32;
    const int x = threadIdx.x, y = threadIdx.y;  // 32x8
    float psum = 0.f;
#pragma unroll
    for (int i = 0; i < 32; i += 8) {
        int k = k0 + y + i;
        float v = W2[(size_t)k * HIDD + n0 + x];
        t[y + i][x] = v * S[k];
        psum += T[k] * v;
    }
    red[y][x] = psum;
    __syncthreads();
#pragma unroll
    for (int i = 0; i < 32; i += 8) {
        float v = t[x][y + i];
        __nv_bfloat16 h = __float2bfloat16(v);
        size_t o = (size_t)(n0 + y + i) * HIDD + k0 + x;
        W2h[o] = h;
        W2l[o] = __float2bfloat16(v - __bfloat162float(h));
    }
    if (y == 0) {
        float tot = 0.f;
#pragma unroll
        for (int g = 0; g < 8; ++g) tot += red[g][x];
        atomicAdd(&bias2[n0 + x], tot);
    }
}

// ---------------- single-pass flash attention, 512 threads -----------------
// tile 32 x 512 fp32 (stride 516), double-buffered cp.async, length-pruned.
// pass1: warp = 32-float d-slice (16 parts), lane = n.
// accumulate: thread owns one d column for all 8 heads.
#define ATT_TSTR 516
#define ATT_TILEF (32 * ATT_TSTR)
#define ATT_TILE_OFF 8480
#define ATTN_SMEM ((ATT_TILE_OFF + 2 * ATT_TILEF) * 4)   // 166016 B

__global__ __launch_bounds__(512) void attn_kernel(
    const float* __restrict__ nb, const float* __restrict__ r,
    const int* __restrict__ lengths,
    __nv_bfloat16* __restrict__ ch, __nv_bfloat16* __restrict__ cl)
{
    extern __shared__ float sm[];
    float* r_s  = sm;                  // [8][512]
    float* sc   = sm + 4096;           // [32][8]
    float* stg  = sm + 4352;           // [16][32][8]
    float* mh   = sm + 8448;           // [8]
    float* ssum = sm + 8456;           // [8]
    float* alf  = sm + 8464;           // [8]
    float* tile = sm + ATT_TILE_OFF;   // 2 x [32][516]

    const int b = blockIdx.x, tid = threadIdx.x;
    const int wid = tid >> 5, lane = tid & 31;
    const float NEG = -INFINITY;
    const float* nbb = nb + (size_t)b * Nn * Dd;
    const int len = lengths[b];
    const int nT = (len + 31) >> 5;

    {
        const float4* rg = (const float4*)(r + (size_t)b * 4096);
        float4* r4 = (float4*)r_s;
        for (int i = tid; i < 1024; i += 512) r4[i] = rg[i];
    }
    if (tid < 8) { mh[tid] = NEG; ssum[tid] = 0.f; }

    const uint32_t tbase = smem_u32(sm) + ATT_TILE_OFF * 4;
    auto issueTile = [&](int t) {
        uint32_t dst = tbase + (uint32_t)(t & 1) * (ATT_TILEF * 4);
        const float* src = nbb + (size_t)t * 32 * Dd;
#pragma unroll
        for (int i = 0; i < 8; i++) {
            int idx = tid + i * 512;
            int n = idx >> 7, c = idx & 127;
            cpasync16(dst + (uint32_t)n * (ATT_TSTR * 4) + (uint32_t)c * 16,
                      src + (size_t)n * Dd + c * 4);
        }
        cpcommit();
    };
    issueTile(0);
    if (nT > 1) issueTile(1);

    float acc[8];
#pragma unroll
    for (int h = 0; h < 8; h++) acc[h] = 0.f;

    for (int t = 0; t < nT; ++t) {
        if (t + 1 < nT) cpwait<1>(); else cpwait<0>();
        __syncthreads();
        const float* tb = tile + (t & 1) * ATT_TILEF;

        // ---- scores: warp = 32-float d-slice (wid 0..15), lane = n ----
        {
            float part[8] = {0.f, 0.f, 0.f, 0.f, 0.f, 0.f, 0.f, 0.f};
            const float4* trow = (const float4*)(tb + lane * ATT_TSTR) + wid * 8;
            const float4* rb = (const float4*)r_s;
#pragma unroll
            for (int i = 0; i < 8; i++) {
                float4 tv = trow[i];
#pragma unroll
                for (int h = 0; h < 8; h++) {
                    float4 rv = rb[h * 128 + wid * 8 + i];
                    part[h] += tv.x * rv.x + tv.y * rv.y + tv.z * rv.z + tv.w * rv.w;
                }
            }
            float* sp = stg + (wid * 32 + lane) * 8;
            *(float4*)sp = make_float4(part[0], part[1], part[2], part[3]);
            *(float4*)(sp + 4) = make_float4(part[4], part[5], part[6], part[7]);
        }
        __syncthreads();
        // ---- reduce across 16 d-parts: thread (n, h) for tid < 256 ----
        if (tid < 256) {
            int n = tid >> 3, h = tid & 7;
            float s = 0.f;
#pragma unroll
            for (int dp = 0; dp < 16; dp++) s += stg[dp * 256 + n * 8 + h];
            sc[n * 8 + h] = s;
        }
        __syncthreads();
        // ---- online softmax update: warps 0-7 = heads ----
        if (wid < 8) {
            int h = wid, n = lane;
            bool valid = (t * 32 + n) < len;
            float v = valid ? sc[n * 8 + h] : NEG;
            float mx = v;
#pragma unroll
            for (int o = 16; o; o >>= 1)
                mx = fmaxf(mx, __shfl_xor_sync(0xffffffffu, mx, o));
            float m_old = mh[h];
            float m_new = fmaxf(m_old, mx);
            float p = valid ? expf(v - m_new) : 0.f;
            float ps = p;
#pragma unroll
            for (int o = 16; o; o >>= 1)
                ps += __shfl_xor_sync(0xffffffffu, ps, o);
            float a = (m_old == NEG) ? 0.f : expf(m_old - m_new);
            if (lane == 0) {
                mh[h] = m_new;
                ssum[h] = ssum[h] * a + ps;
                alf[h] = a;
            }
            sc[n * 8 + h] = p;
        }
        __syncthreads();
        // ---- accumulate: thread owns d = tid for all heads ----
        {
#pragma unroll
            for (int h = 0; h < 8; h++) acc[h] *= alf[h];
#pragma unroll 8
            for (int n = 0; n < 32; ++n) {
                float tv = tb[n * ATT_TSTR + tid];
                float4 p0 = *(const float4*)(sc + n * 8);
                float4 p1 = *(const float4*)(sc + n * 8 + 4);
                acc[0] += p0.x * tv; acc[1] += p0.y * tv;
                acc[2] += p0.z * tv; acc[3] += p0.w * tv;
                acc[4] += p1.x * tv; acc[5] += p1.y * tv;
                acc[6] += p1.z * tv; acc[7] += p1.w * tv;
            }
        }
        __syncthreads();
        if (t + 2 < nT) issueTile(t + 2);
    }

    __nv_bfloat16* cbh = ch + (size_t)b * 4096;
    __nv_bfloat16* cbl = cl + (size_t)b * 4096;
#pragma unroll
    for (int h = 0; h < 8; h++) {
        float v = acc[h] * (1.f / ssum[h]);
        __nv_bfloat16 hi = __float2bfloat16(v);
        cbh[h * 512 + tid] = hi;
        cbl[h * 512 + tid] = __float2bfloat16(v - __bfloat162float(hi));
    }
}

// ---------------- launch ----------------
extern "C" void kernel_launch(void* const* d_in, const int* in_sizes, int n_in,
                              void* d_out, int out_size)
{
    const float* catalog = (const float*)d_in[0];
    const float* neighbors = (const float*)d_in[1];
    const int*   lengths = (const int*)d_in[2];
    const float* W1 = (const float*)d_in[3];
    const float* b1 = (const float*)d_in[4];
    const float* gamma = (const float*)d_in[5];
    const float* beta = (const float*)d_in[6];
    const float* W2 = (const float*)d_in[7];
    const float* b2 = (const float*)d_in[8];
    const float* W3 = (const float*)d_in[9];
    const float* b3 = (const float*)d_in[10];
    const float* Wq = (const float*)d_in[11];
    const float* bq = (const float*)d_in[12];
    const float* Wk = (const float*)d_in[13];
    // d_in[14] = bk: constant per (b,h) across n -> cancels in softmax
    const float* Wv = (const float*)d_in[15];
    const float* bv = (const float*)d_in[16];
    const float* Wo = (const float*)d_in[17];
    const float* bo = (const float*)d_in[18];
    float* out = (float*)d_out;

    __nv_bfloat16 *cath, *catl, *H1h, *H1l, *H2h, *H2l, *embh, *embl;
    __nv_bfloat16 *qh, *ql, *ch, *cl, *ctxh, *ctxl;
    __nv_bfloat16 *W1Th, *W1Tl, *W2h, *W2l, *W3Th, *W3Tl;
    __nv_bfloat16 *WqTh, *WqTl, *Wkh, *Wkl, *WvTh, *WvTl, *WoTh, *WoTl;
    float *r, *S, *T, *bias2;
    cudaGetSymbolAddress((void**)&cath, g_cath);
    cudaGetSymbolAddress((void**)&catl, g_catl);
    cudaGetSymbolAddress((void**)&H1h, g_H1h);
    cudaGetSymbolAddress((void**)&H1l, g_H1l);
    cudaGetSymbolAddress((void**)&H2h, g_H2h);
    cudaGetSymbolAddress((void**)&H2l, g_H2l);
    cudaGetSymbolAddress((void**)&embh, g_embh);
    cudaGetSymbolAddress((void**)&embl, g_embl);
    cudaGetSymbolAddress((void**)&qh, g_qh);
    cudaGetSymbolAddress((void**)&ql, g_ql);
    cudaGetSymbolAddress((void**)&ch, g_ch);
    cudaGetSymbolAddress((void**)&cl, g_cl);
    cudaGetSymbolAddress((void**)&ctxh, g_ctxh);
    cudaGetSymbolAddress((void**)&ctxl, g_ctxl);
    cudaGetSymbolAddress((void**)&W1Th, g_W1Th);
    cudaGetSymbolAddress((void**)&W1Tl, g_W1Tl);
    cudaGetSymbolAddress((void**)&W2h, g_W2h);
    cudaGetSymbolAddress((void**)&W2l, g_W2l);
    cudaGetSymbolAddress((void**)&W3Th, g_W3Th);
    cudaGetSymbolAddress((void**)&W3Tl, g_W3Tl);
    cudaGetSymbolAddress((void**)&WqTh, g_WqTh);
    cudaGetSymbolAddress((void**)&WqTl, g_WqTl);
    cudaGetSymbolAddress((void**)&Wkh, g_Wkh);
    cudaGetSymbolAddress((void**)&Wkl, g_Wkl);
    cudaGetSymbolAddress((void**)&WvTh, g_WvTh);
    cudaGetSymbolAddress((void**)&WvTl, g_WvTl);
    cudaGetSymbolAddress((void**)&WoTh, g_WoTh);
    cudaGetSymbolAddress((void**)&WoTl, g_WoTl);
    cudaGetSymbolAddress((void**)&r, g_r);
    cudaGetSymbolAddress((void**)&S, g_bnS);
    cudaGetSymbolAddress((void**)&T, g_bnT);
    cudaGetSymbolAddress((void**)&bias2, g_bias2);

    constexpr int STAGE128 = 36864 + 2 * 128 * 144;  // 73728
    constexpr int STAGE64  = 36864 + 2 * 64 * 144;   // 55296
    constexpr int SM128 = 3 * STAGE128;              // 221184
    constexpr int SM64  = 3 * STAGE64;               // 165888
    cudaFuncSetAttribute(bgemm<128, true, 1>,
                         cudaFuncAttributeMaxDynamicSharedMemorySize, SM128);
    cudaFuncSetAttribute(bgemm<64, false, 1>,
                         cudaFuncAttributeMaxDynamicSharedMemorySize, SM64);
    cudaFuncSetAttribute(bgemm<64, false, 0>,
                         cudaFuncAttributeMaxDynamicSharedMemorySize, SM64);
    cudaFuncSetAttribute(attn_kernel,
                         cudaFuncAttributeMaxDynamicSharedMemorySize, ATTN_SMEM);

    // ---- prep ----
    transposeSplit<<<dim3(HIDD / 32, Dd / 32), dim3(32, 8)>>>(W1, W1Th, W1Tl,
                                                              Dd, HIDD);
    splitOnly<<<(Bb * Dd / 4) / 256, 256>>>(catalog, cath, catl, Bb * Dd / 4);
    transposeSplit<<<dim3(Dd / 32, HIDD / 32), dim3(32, 8)>>>(W3, W3Th, W3Tl,
                                                              HIDD, Dd);
    transposeSplit512x3<<<dim3(16, 16, 3), dim3(32, 8)>>>(
        Wq, Wv, Wo, WqTh, WqTl, WvTh, WvTl, WoTh, WoTl);
    splitOnly<<<(Dd * Dd / 4) / 256, 256>>>(Wk, Wkh, Wkl, Dd * Dd / 4);

    // ---- FFN ----
    bgemm<128, true, 1><<<dim3(16, 16, 1), 256, SM128>>>(
        cath, catl, Dd, 0, W1Th, W1Tl, Dd, 0,
        nullptr, H1h, H1l, HIDD, 0, b1, 0, Dd, 1.f);
    bn_stats_kernel<<<HIDD / 16, 256>>>(H1h, H1l, gamma, beta, b2, S, T, bias2);
    w2prepFused<<<dim3(HIDD / 32, HIDD / 32), dim3(32, 8)>>>(
        W2, S, T, W2h, W2l, bias2);
    bgemm<128, true, 1><<<dim3(16, 16, 1), 256, SM128>>>(
        H1h, H1l, HIDD, 0, W2h, W2l, HIDD, 0,
        nullptr, H2h, H2l, HIDD, 0, bias2, 0, HIDD, 1.f);
    bgemm<64, false, 1><<<dim3(8, 16, 1), 256, SM64>>>(
        H2h, H2l, HIDD, 0, W3Th, W3Tl, HIDD, 0,
        nullptr, embh, embl, Dd, 0, b3, 0, HIDD, 1.f);

    // ---- q = emb @ Wq + bq ----
    bgemm<64, false, 1><<<dim3(8, 16, 1), 256, SM64>>>(
        embh, embl, Dd, 0, WqTh, WqTl, Dd, 0,
        nullptr, qh, ql, Dd, 0, bq, 0, Dd, 1.f);

    // ---- r[b,h,d] = (1/8) * sum_j q[b,h,j] * Wk[d, h*64+j] ----
    bgemm<64, false, 0><<<dim3(8, 16, 8), 256, SM64>>>(
        qh, ql, Dd, DHh, Wkh, Wkl, Dd, DHh,
        r, nullptr, nullptr, Hh * Dd, Dd, nullptr, 0, DHh, 0.125f);

    // ---- single-pass flash attention (length-pruned, 512 threads) ----
    attn_kernel<<<Bb, 512, ATTN_SMEM>>>(neighbors, r, lengths, ch, cl);

    // ---- ctx = c @ Wv + bv (per head) ----
    bgemm<64, false, 1><<<dim3(1, 16, 8), 256, SM64>>>(
        ch, cl, Hh * Dd, Dd, WvTh, WvTl, Dd, (long)DHh * Dd,
        nullptr, ctxh, ctxl, Dd, DHh, bv, DHh, Dd, 1.f);

    // ---- out = ctx @ Wo + bo ----
    bgemm<64, false, 0><<<dim3(8, 16, 1), 256, SM64>>>(
        ctxh, ctxl, Dd, 0, WoTh, WoTl, Dd, 0,
        out, nullptr, nullptr, Dd, 0, bo, 0, Dd, 1.f);
}

// round 10
// speedup vs baseline: 1.0380x; 1.0380x over previous
#include <cuda_runtime.h>
#include <cuda_bf16.h>
#include <math.h>
#include <stdint.h>

// Problem dims (fixed)
#define Bb   2048
#define Nn   128
#define Dd   512
#define HIDD 2048
#define Hh   8
#define DHh  64

// ---------------- scratch (device globals; no allocations) ----------------
__device__ __nv_bfloat16 g_cath[Bb * Dd],  g_catl[Bb * Dd];
__device__ __nv_bfloat16 g_H1h[Bb * HIDD], g_H1l[Bb * HIDD];
__device__ __nv_bfloat16 g_H2h[Bb * HIDD], g_H2l[Bb * HIDD];
__device__ __nv_bfloat16 g_embh[Bb * Dd],  g_embl[Bb * Dd];
__device__ __nv_bfloat16 g_qh[Bb * Dd],    g_ql[Bb * Dd];
__device__ __nv_bfloat16 g_ch[Bb * Hh * Dd], g_cl[Bb * Hh * Dd];
__device__ __nv_bfloat16 g_ctxh[Bb * Dd],  g_ctxl[Bb * Dd];
__device__ __nv_bfloat16 g_W1Th[HIDD * Dd], g_W1Tl[HIDD * Dd];
__device__ __nv_bfloat16 g_W2h[HIDD * HIDD], g_W2l[HIDD * HIDD];
__device__ __nv_bfloat16 g_W3Th[Dd * HIDD], g_W3Tl[Dd * HIDD];
__device__ __nv_bfloat16 g_WqTh[Dd * Dd],  g_WqTl[Dd * Dd];
__device__ __nv_bfloat16 g_Wkh[Dd * Dd],   g_Wkl[Dd * Dd];
__device__ __nv_bfloat16 g_WvTh[Dd * Dd],  g_WvTl[Dd * Dd];
__device__ __nv_bfloat16 g_WoTh[Dd * Dd],  g_WoTl[Dd * Dd];
__device__ float g_r[Bb * Hh * Dd];
__device__ float g_bnS[HIDD];
__device__ float g_bnT[HIDD];
__device__ float g_bias2[HIDD];

// ================= helpers =================
__device__ __forceinline__ uint32_t smem_u32(const void* p) {
    uint32_t a;
    asm("{ .reg .u64 t; cvta.to.shared.u64 t, %1; cvt.u32.u64 %0, t; }"
        : "=r"(a) : "l"(p));
    return a;
}
__device__ __forceinline__ void cpasync16(uint32_t dst, const void* src) {
    asm volatile("cp.async.cg.shared.global [%0], [%1], 16;"
                 :: "r"(dst), "l"(src) : "memory");
}
__device__ __forceinline__ void cpcommit() {
    asm volatile("cp.async.commit_group;" ::: "memory");
}
template <int N>
__device__ __forceinline__ void cpwait() {
    asm volatile("cp.async.wait_group %0;" :: "n"(N) : "memory");
}
__device__ __forceinline__ void ldm4(uint32_t* r, uint32_t addr) {
    asm volatile("ldmatrix.sync.aligned.m8n8.x4.shared.b16 {%0,%1,%2,%3}, [%4];"
                 : "=r"(r[0]), "=r"(r[1]), "=r"(r[2]), "=r"(r[3]) : "r"(addr));
}
__device__ __forceinline__ void mma16816(float* c, const uint32_t* a,
                                         const uint32_t* b) {
    asm volatile(
        "mma.sync.aligned.m16n8k16.row.col.f32.bf16.bf16.f32 "
        "{%0,%1,%2,%3}, {%4,%5,%6,%7}, {%8,%9}, {%0,%1,%2,%3};"
        : "+f"(c[0]), "+f"(c[1]), "+f"(c[2]), "+f"(c[3])
        : "r"(a[0]), "r"(a[1]), "r"(a[2]), "r"(a[3]), "r"(b[0]), "r"(b[1]));
}
__device__ __forceinline__ void split_store(float x, float y,
                                            __nv_bfloat16* ph,
                                            __nv_bfloat16* pl) {
    __nv_bfloat162 h = __floats2bfloat162_rn(x, y);
    float rx = x - __bfloat162float(h.x);
    float ry = y - __bfloat162float(h.y);
    __nv_bfloat162 l = __floats2bfloat162_rn(rx, ry);
    *reinterpret_cast<uint32_t*>(ph) = *reinterpret_cast<uint32_t*>(&h);
    *reinterpret_cast<uint32_t*>(pl) = *reinterpret_cast<uint32_t*>(&l);
}
// fast accurate tanh via __expf (err ~1e-7)
__device__ __forceinline__ float ftanh(float x) {
    float e = __expf(-2.f * fabsf(x));
    float r = __fdividef(1.f - e, 1.f + e);
    return copysignf(r, x);
}

// ================= bf16x3 GEMM, TBK=64, 3-stage cp.async, 1 sync/iter ======
template <int TBN, bool DOTANH, int OUTMODE>
__global__ void __launch_bounds__(256)
bgemm(const __nv_bfloat16* __restrict__ Ah, const __nv_bfloat16* __restrict__ Al,
      int lda, long sAz,
      const __nv_bfloat16* __restrict__ Bh, const __nv_bfloat16* __restrict__ Bl,
      int ldb, long sBz,
      float* __restrict__ C, __nv_bfloat16* __restrict__ Ch,
      __nv_bfloat16* __restrict__ Cl, int ldc, long sCz,
      const float* __restrict__ bias, long sBiasz, int K, float scale)
{
    constexpr int TBM = 128, TBK = 64;
    constexpr int WN = TBN / 4;
    constexpr int NF = WN / 8;
    constexpr int STRIDE = 144;
    constexpr int OA_L = TBM * STRIDE;
    constexpr int OB_H = 2 * TBM * STRIDE;
    constexpr int OB_L = OB_H + TBN * STRIDE;
    constexpr int STAGE = OB_H + 2 * TBN * STRIDE;

    extern __shared__ __align__(16) char dynsm[];
    const uint32_t sb0 = smem_u32(dynsm);

    const int tid = threadIdx.x, wid = tid >> 5, lane = tid & 31;
    const int wm = wid >> 2, wn = wid & 3;

    Ah += (size_t)blockIdx.z * sAz + (size_t)blockIdx.y * TBM * lda;
    Al += (size_t)blockIdx.z * sAz + (size_t)blockIdx.y * TBM * lda;
    Bh += (size_t)blockIdx.z * sBz + (size_t)blockIdx.x * TBN * ldb;
    Bl += (size_t)blockIdx.z * sBz + (size_t)blockIdx.x * TBN * ldb;

    const uint32_t aoff = (uint32_t)(wm * 64 + (lane & 15)) * STRIDE
                        + (uint32_t)((lane >> 4) * 8) * 2;
    const uint32_t boff = (uint32_t)(wn * WN + ((lane >> 4) & 1) * 8 + (lane & 7))
                          * STRIDE
                        + (uint32_t)(((lane >> 3) & 1) * 8) * 2;

    float acc[4][NF][4];
#pragma unroll
    for (int i = 0; i < 4; i++)
#pragma unroll
        for (int j = 0; j < NF; j++)
#pragma unroll
            for (int e = 0; e < 4; e++) acc[i][j][e] = 0.f;

    auto issueStage = [&](int kt, int buf) {
        const uint32_t sb = sb0 + buf * STAGE;
        const int k0 = kt * TBK;
#pragma unroll
        for (int i = 0; i < 4; i++) {
            int idx = tid + i * 256;
            int r = idx >> 3, cc = idx & 7;
            const size_t go = (size_t)r * lda + k0 + cc * 8;
            const uint32_t so = (uint32_t)r * STRIDE + cc * 16;
            cpasync16(sb + so, Ah + go);
            cpasync16(sb + OA_L + so, Al + go);
        }
#pragma unroll
        for (int i = 0; i < TBN / 32; i++) {
            int idx = tid + i * 256;
            int r = idx >> 3, cc = idx & 7;
            const size_t go = (size_t)r * ldb + k0 + cc * 8;
            const uint32_t so = (uint32_t)r * STRIDE + cc * 16;
            cpasync16(sb + OB_H + so, Bh + go);
            cpasync16(sb + OB_L + so, Bl + go);
        }
        cpcommit();
    };

    auto compute = [&](int buf) {
        const uint32_t sb = sb0 + buf * STAGE;
#pragma unroll
        for (int kh = 0; kh < 4; ++kh) {
            const uint32_t kb = (uint32_t)kh * 32;
            uint32_t bh[NF][2], bl[NF][2];
#pragma unroll
            for (int p = 0; p < NF / 2; ++p) {
                uint32_t r4[4];
                ldm4(r4, sb + OB_H + boff + p * 16u * STRIDE + kb);
                bh[2 * p][0] = r4[0]; bh[2 * p][1] = r4[1];
                bh[2 * p + 1][0] = r4[2]; bh[2 * p + 1][1] = r4[3];
                ldm4(r4, sb + OB_L + boff + p * 16u * STRIDE + kb);
                bl[2 * p][0] = r4[0]; bl[2 * p][1] = r4[1];
                bl[2 * p + 1][0] = r4[2]; bl[2 * p + 1][1] = r4[3];
            }
#pragma unroll
            for (int mf = 0; mf < 4; ++mf) {
                uint32_t ah[4], al[4];
                ldm4(ah, sb + aoff + (uint32_t)mf * 16u * STRIDE + kb);
                ldm4(al, sb + OA_L + aoff + (uint32_t)mf * 16u * STRIDE + kb);
#pragma unroll
                for (int nf = 0; nf < NF; ++nf) {
                    mma16816(acc[mf][nf], ah, bh[nf]);
                    mma16816(acc[mf][nf], ah, bl[nf]);
                    mma16816(acc[mf][nf], al, bh[nf]);
                }
            }
        }
    };

    const int KT = K / TBK;
    issueStage(0, 0);
    if (KT > 1) issueStage(1, 1);
    for (int kt = 0; kt < KT; ++kt) {
        if (kt + 1 < KT) cpwait<1>(); else cpwait<0>();
        __syncthreads();
        if (kt + 2 < KT) issueStage(kt + 2, (kt + 2) % 3);
        compute(kt % 3);
    }

    const float* bp = bias ? bias + (size_t)blockIdx.z * sBiasz
                           + (size_t)blockIdx.x * TBN
                         : nullptr;
    const size_t cbase = (size_t)blockIdx.z * sCz
                       + (size_t)blockIdx.y * TBM * ldc
                       + (size_t)blockIdx.x * TBN;
    const int r1 = lane >> 2, c1 = (lane & 3) * 2;
#pragma unroll
    for (int mf = 0; mf < 4; ++mf) {
#pragma unroll
        for (int nf = 0; nf < NF; ++nf) {
            int col = wn * WN + nf * 8 + c1;
            float bx = bp ? bp[col] : 0.f, by = bp ? bp[col + 1] : 0.f;
            int row0 = wm * 64 + mf * 16 + r1;
            float2 v0, v1;
            v0.x = acc[mf][nf][0] * scale + bx;
            v0.y = acc[mf][nf][1] * scale + by;
            v1.x = acc[mf][nf][2] * scale + bx;
            v1.y = acc[mf][nf][3] * scale + by;
            if (DOTANH) {
                v0.x = ftanh(v0.x); v0.y = ftanh(v0.y);
                v1.x = ftanh(v1.x); v1.y = ftanh(v1.y);
            }
            size_t o0 = cbase + (size_t)row0 * ldc + col;
            size_t o1 = cbase + (size_t)(row0 + 8) * ldc + col;
            if (OUTMODE == 0) {
                *(float2*)(C + o0) = v0;
                *(float2*)(C + o1) = v1;
            } else {
                split_store(v0.x, v0.y, Ch + o0, Cl + o0);
                split_store(v1.x, v1.y, Ch + o1, Cl + o1);
            }
        }
    }
}

// ---------------- merged weight prep: transpose+split for 5 weights --------
// tiles: W1 [512x2048]->1024, W3 [2048x512]->1024, Wq/Wv/Wo [512x512]->256 ea
__global__ void transposeSplitAll(
    const float* __restrict__ W1, const float* __restrict__ W3,
    const float* __restrict__ Wq, const float* __restrict__ Wv,
    const float* __restrict__ Wo,
    __nv_bfloat16* __restrict__ W1Th, __nv_bfloat16* __restrict__ W1Tl,
    __nv_bfloat16* __restrict__ W3Th, __nv_bfloat16* __restrict__ W3Tl,
    __nv_bfloat16* __restrict__ WqTh, __nv_bfloat16* __restrict__ WqTl,
    __nv_bfloat16* __restrict__ WvTh, __nv_bfloat16* __restrict__ WvTl,
    __nv_bfloat16* __restrict__ WoTh, __nv_bfloat16* __restrict__ WoTl)
{
    int bid = blockIdx.x;
    const float* in;
    __nv_bfloat16 *oh, *ol;
    int R, C, bx, by;
    if (bid < 1024) {
        in = W1; oh = W1Th; ol = W1Tl; R = 512; C = 2048;
        bx = (bid & 63) * 32; by = (bid >> 6) * 32;
    } else if (bid < 2048) {
        int b = bid - 1024;
        in = W3; oh = W3Th; ol = W3Tl; R = 2048; C = 512;
        bx = (b & 15) * 32; by = (b >> 4) * 32;
    } else {
        int b = bid - 2048;
        int j = b >> 8;  // 0,1,2
        in = j == 0 ? Wq : j == 1 ? Wv : Wo;
        oh = j == 0 ? WqTh : j == 1 ? WvTh : WoTh;
        ol = j == 0 ? WqTl : j == 1 ? WvTl : WoTl;
        R = 512; C = 512;
        b &= 255;
        bx = (b & 15) * 32; by = (b >> 4) * 32;
    }
    __shared__ float t[32][33];
    int x = threadIdx.x, y = threadIdx.y;  // 32x8
#pragma unroll
    for (int i = 0; i < 32; i += 8)
        t[y + i][x] = in[(size_t)(by + y + i) * C + bx + x];
    __syncthreads();
#pragma unroll
    for (int i = 0; i < 32; i += 8) {
        float v = t[x][y + i];
        __nv_bfloat16 h = __float2bfloat16(v);
        size_t o = (size_t)(bx + y + i) * R + by + x;
        oh[o] = h;
        ol[o] = __float2bfloat16(v - __bfloat162float(h));
    }
}

// ---------------- merged split: catalog + Wk ----------------
#define CAT_F4 (Bb * Dd / 4)   // 262144
#define WK_F4  (Dd * Dd / 4)   // 65536
__global__ void splitAll(const float* __restrict__ catalog,
                         const float* __restrict__ Wk,
                         __nv_bfloat16* __restrict__ cath,
                         __nv_bfloat16* __restrict__ catl,
                         __nv_bfloat16* __restrict__ Wkh,
                         __nv_bfloat16* __restrict__ Wkl)
{
    int i = blockIdx.x * blockDim.x + threadIdx.x;
    const float* in;
    __nv_bfloat16 *oh, *ol;
    int j;
    if (i < CAT_F4) { in = catalog; oh = cath; ol = catl; j = i; }
    else { in = Wk; oh = Wkh; ol = Wkl; j = i - CAT_F4; }
    float4 v = ((const float4*)in)[j];
    split_store(v.x, v.y, oh + (size_t)j * 4, ol + (size_t)j * 4);
    split_store(v.z, v.w, oh + (size_t)j * 4 + 2, ol + (size_t)j * 4 + 2);
}

// ---------------- BatchNorm stats (also inits bias2 = b2) ----------------
__global__ void bn_stats_kernel(const __nv_bfloat16* __restrict__ H1h,
                                const __nv_bfloat16* __restrict__ H1l,
                                const float* __restrict__ gamma,
                                const float* __restrict__ beta,
                                const float* __restrict__ b2,
                                float* __restrict__ S, float* __restrict__ T,
                                float* __restrict__ bias2)
{
    __shared__ float ss[16][16], sq[16][16];
    const int col0 = blockIdx.x * 16;
    const int c = threadIdx.x & 15, rg = threadIdx.x >> 4;
    float s = 0.f, q = 0.f;
#pragma unroll 4
    for (int i = 0; i < 128; ++i) {
        size_t idx = (size_t)(rg * 128 + i) * HIDD + col0 + c;
        float v = __bfloat162float(H1h[idx]) + __bfloat162float(H1l[idx]);
        s += v;
        q += v * v;
    }
    ss[rg][c] = s;
    sq[rg][c] = q;
    __syncthreads();
    if (threadIdx.x < 16) {
        float st = 0.f, qt = 0.f;
#pragma unroll
        for (int g = 0; g < 16; ++g) { st += ss[g][threadIdx.x]; qt += sq[g][threadIdx.x]; }
        float mu = st / 2048.f;
        float var = qt / 2048.f - mu * mu;
        float rstd = rsqrtf(var + 1e-5f);
        float sc = gamma[col0 + threadIdx.x] * rstd;
        S[col0 + threadIdx.x] = sc;
        T[col0 + threadIdx.x] = beta[col0 + threadIdx.x] - mu * sc;
        bias2[col0 + threadIdx.x] = b2[col0 + threadIdx.x];
    }
}

// ---------------- fused W2 prep ----------------
__global__ void w2prepFused(const float* __restrict__ W2,
                            const float* __restrict__ S,
                            const float* __restrict__ T,
                            __nv_bfloat16* __restrict__ W2h,
                            __nv_bfloat16* __restrict__ W2l,
                            float* __restrict__ bias2)
{
    __shared__ float t[32][33];
    __shared__ float red[8][33];
    const int n0 = blockIdx.x * 32, k0 = blockIdx.y * 32;
    const int x = threadIdx.x, y = threadIdx.y;  // 32x8
    float psum = 0.f;
#pragma unroll
    for (int i = 0; i < 32; i += 8) {
        int k = k0 + y + i;
        float v = W2[(size_t)k * HIDD + n0 + x];
        t[y + i][x] = v * S[k];
        psum += T[k] * v;
    }
    red[y][x] = psum;
    __syncthreads();
#pragma unroll
    for (int i = 0; i < 32; i += 8) {
        float v = t[x][y + i];
        __nv_bfloat16 h = __float2bfloat16(v);
        size_t o = (size_t)(n0 + y + i) * HIDD + k0 + x;
        W2h[o] = h;
        W2l[o] = __float2bfloat16(v - __bfloat162float(h));
    }
    if (y == 0) {
        float tot = 0.f;
#pragma unroll
        for (int g = 0; g < 8; ++g) tot += red[g][x];
        atomicAdd(&bias2[n0 + x], tot);
    }
}

// ---------------- single-pass flash attention, 256 threads (R8 proven) -----
#define ATT_TSTR 516
#define ATT_TILEF (32 * ATT_TSTR)
#define ATT_TILE_OFF 6432
#define ATTN_SMEM ((ATT_TILE_OFF + 2 * ATT_TILEF) * 4)   // 157824 B

__global__ __launch_bounds__(256) void attn_kernel(
    const float* __restrict__ nb, const float* __restrict__ r,
    const int* __restrict__ lengths,
    __nv_bfloat16* __restrict__ ch, __nv_bfloat16* __restrict__ cl)
{
    extern __shared__ float sm[];
    float* r_s  = sm;                  // [8][512]
    float* sc   = sm + 4096;           // [32][8]
    float* stg  = sm + 4352;           // [8][32][8]
    float* mh   = sm + 6400;           // [8]
    float* ssum = sm + 6408;           // [8]
    float* alf  = sm + 6416;           // [8]
    float* tile = sm + ATT_TILE_OFF;   // 2 x [32][516]

    const int b = blockIdx.x, tid = threadIdx.x;
    const int wid = tid >> 5, lane = tid & 31;
    const float NEG = -INFINITY;
    const float* nbb = nb + (size_t)b * Nn * Dd;
    const int len = lengths[b];
    const int nT = (len + 31) >> 5;

    {
        const float4* rg = (const float4*)(r + (size_t)b * 4096);
        float4* r4 = (float4*)r_s;
        for (int i = tid; i < 1024; i += 256) r4[i] = rg[i];
    }
    if (tid < 8) { mh[tid] = NEG; ssum[tid] = 0.f; }

    const uint32_t tbase = smem_u32(sm) + ATT_TILE_OFF * 4;
    auto issueTile = [&](int t) {
        uint32_t dst = tbase + (uint32_t)(t & 1) * (ATT_TILEF * 4);
        const float* src = nbb + (size_t)t * 32 * Dd;
#pragma unroll
        for (int i = 0; i < 16; i++) {
            int idx = tid + i * 256;
            int n = idx >> 7, c = idx & 127;
            cpasync16(dst + (uint32_t)n * (ATT_TSTR * 4) + (uint32_t)c * 16,
                      src + (size_t)n * Dd + c * 4);
        }
        cpcommit();
    };
    issueTile(0);
    if (nT > 1) issueTile(1);

    float acc[8][2];
#pragma unroll
    for (int h = 0; h < 8; h++) { acc[h][0] = 0.f; acc[h][1] = 0.f; }
    const int d0 = 2 * tid;

    for (int t = 0; t < nT; ++t) {
        if (t + 1 < nT) cpwait<1>(); else cpwait<0>();
        __syncthreads();
        const float* tb = tile + (t & 1) * ATT_TILEF;

        // ---- scores: warp = d-part (64 floats), lane = n ----
        {
            float part[8] = {0.f, 0.f, 0.f, 0.f, 0.f, 0.f, 0.f, 0.f};
            const float4* trow = (const float4*)(tb + lane * ATT_TSTR + wid * 64);
            const float4* rb = (const float4*)r_s + wid * 16;
#pragma unroll
            for (int i = 0; i < 16; i++) {
                float4 tv = trow[i];
#pragma unroll
                for (int h = 0; h < 8; h++) {
                    float4 rv = rb[h * 128 + i];
                    part[h] += tv.x * rv.x + tv.y * rv.y + tv.z * rv.z + tv.w * rv.w;
                }
            }
            float* sp = stg + (wid * 32 + lane) * 8;
            *(float4*)sp = make_float4(part[0], part[1], part[2], part[3]);
            *(float4*)(sp + 4) = make_float4(part[4], part[5], part[6], part[7]);
        }
        __syncthreads();
        // ---- reduce across 8 d-parts ----
        {
            int n = tid >> 3, h = tid & 7;
            float s = 0.f;
#pragma unroll
            for (int dp = 0; dp < 8; dp++) s += stg[dp * 256 + n * 8 + h];
            sc[n * 8 + h] = s;
        }
        __syncthreads();
        // ---- online softmax update: warp = head ----
        {
            int h = wid, n = lane;
            bool valid = (t * 32 + n) < len;
            float v = valid ? sc[n * 8 + h] : NEG;
            float mx = v;
#pragma unroll
            for (int o = 16; o; o >>= 1)
                mx = fmaxf(mx, __shfl_xor_sync(0xffffffffu, mx, o));
            float m_old = mh[h];
            float m_new = fmaxf(m_old, mx);
            float p = valid ? expf(v - m_new) : 0.f;
            float ps = p;
#pragma unroll
            for (int o = 16; o; o >>= 1)
                ps += __shfl_xor_sync(0xffffffffu, ps, o);
            float a = (m_old == NEG) ? 0.f : expf(m_old - m_new);
            if (lane == 0) {
                mh[h] = m_new;
                ssum[h] = ssum[h] * a + ps;
                alf[h] = a;
            }
            sc[n * 8 + h] = p;
        }
        __syncthreads();
        // ---- accumulate: thread owns d pair {2t,2t+1} for all heads ----
        {
#pragma unroll
            for (int h = 0; h < 8; h++) {
                float a = alf[h];
                acc[h][0] *= a;
                acc[h][1] *= a;
            }
#pragma unroll 8
            for (int n = 0; n < 32; ++n) {
                float2 tv = *(const float2*)(tb + n * ATT_TSTR + d0);
                float4 p0 = *(const float4*)(sc + n * 8);
                float4 p1 = *(const float4*)(sc + n * 8 + 4);
                acc[0][0] += p0.x * tv.x; acc[0][1] += p0.x * tv.y;
                acc[1][0] += p0.y * tv.x; acc[1][1] += p0.y * tv.y;
                acc[2][0] += p0.z * tv.x; acc[2][1] += p0.z * tv.y;
                acc[3][0] += p0.w * tv.x; acc[3][1] += p0.w * tv.y;
                acc[4][0] += p1.x * tv.x; acc[4][1] += p1.x * tv.y;
                acc[5][0] += p1.y * tv.x; acc[5][1] += p1.y * tv.y;
                acc[6][0] += p1.z * tv.x; acc[6][1] += p1.z * tv.y;
                acc[7][0] += p1.w * tv.x; acc[7][1] += p1.w * tv.y;
            }
        }
        __syncthreads();
        if (t + 2 < nT) issueTile(t + 2);
    }

    __nv_bfloat16* cbh = ch + (size_t)b * 4096;
    __nv_bfloat16* cbl = cl + (size_t)b * 4096;
#pragma unroll
    for (int h = 0; h < 8; h++) {
        float inv = 1.f / ssum[h];
        split_store(acc[h][0] * inv, acc[h][1] * inv,
                    cbh + h * 512 + d0, cbl + h * 512 + d0);
    }
}

// ---------------- launch ----------------
extern "C" void kernel_launch(void* const* d_in, const int* in_sizes, int n_in,
                              void* d_out, int out_size)
{
    const float* catalog = (const float*)d_in[0];
    const float* neighbors = (const float*)d_in[1];
    const int*   lengths = (const int*)d_in[2];
    const float* W1 = (const float*)d_in[3];
    const float* b1 = (const float*)d_in[4];
    const float* gamma = (const float*)d_in[5];
    const float* beta = (const float*)d_in[6];
    const float* W2 = (const float*)d_in[7];
    const float* b2 = (const float*)d_in[8];
    const float* W3 = (const float*)d_in[9];
    const float* b3 = (const float*)d_in[10];
    const float* Wq = (const float*)d_in[11];
    const float* bq = (const float*)d_in[12];
    const float* Wk = (const float*)d_in[13];
    // d_in[14] = bk: constant per (b,h) across n -> cancels in softmax
    const float* Wv = (const float*)d_in[15];
    const float* bv = (const float*)d_in[16];
    const float* Wo = (const float*)d_in[17];
    const float* bo = (const float*)d_in[18];
    float* out = (float*)d_out;

    __nv_bfloat16 *cath, *catl, *H1h, *H1l, *H2h, *H2l, *embh, *embl;
    __nv_bfloat16 *qh, *ql, *ch, *cl, *ctxh, *ctxl;
    __nv_bfloat16 *W1Th, *W1Tl, *W2h, *W2l, *W3Th, *W3Tl;
    __nv_bfloat16 *WqTh, *WqTl, *Wkh, *Wkl, *WvTh, *WvTl, *WoTh, *WoTl;
    float *r, *S, *T, *bias2;
    cudaGetSymbolAddress((void**)&cath, g_cath);
    cudaGetSymbolAddress((void**)&catl, g_catl);
    cudaGetSymbolAddress((void**)&H1h, g_H1h);
    cudaGetSymbolAddress((void**)&H1l, g_H1l);
    cudaGetSymbolAddress((void**)&H2h, g_H2h);
    cudaGetSymbolAddress((void**)&H2l, g_H2l);
    cudaGetSymbolAddress((void**)&embh, g_embh);
    cudaGetSymbolAddress((void**)&embl, g_embl);
    cudaGetSymbolAddress((void**)&qh, g_qh);
    cudaGetSymbolAddress((void**)&ql, g_ql);
    cudaGetSymbolAddress((void**)&ch, g_ch);
    cudaGetSymbolAddress((void**)&cl, g_cl);
    cudaGetSymbolAddress((void**)&ctxh, g_ctxh);
    cudaGetSymbolAddress((void**)&ctxl, g_ctxl);
    cudaGetSymbolAddress((void**)&W1Th, g_W1Th);
    cudaGetSymbolAddress((void**)&W1Tl, g_W1Tl);
    cudaGetSymbolAddress((void**)&W2h, g_W2h);
    cudaGetSymbolAddress((void**)&W2l, g_W2l);
    cudaGetSymbolAddress((void**)&W3Th, g_W3Th);
    cudaGetSymbolAddress((void**)&W3Tl, g_W3Tl);
    cudaGetSymbolAddress((void**)&WqTh, g_WqTh);
    cudaGetSymbolAddress((void**)&WqTl, g_WqTl);
    cudaGetSymbolAddress((void**)&Wkh, g_Wkh);
    cudaGetSymbolAddress((void**)&Wkl, g_Wkl);
    cudaGetSymbolAddress((void**)&WvTh, g_WvTh);
    cudaGetSymbolAddress((void**)&WvTl, g_WvTl);
    cudaGetSymbolAddress((void**)&WoTh, g_WoTh);
    cudaGetSymbolAddress((void**)&WoTl, g_WoTl);
    cudaGetSymbolAddress((void**)&r, g_r);
    cudaGetSymbolAddress((void**)&S, g_bnS);
    cudaGetSymbolAddress((void**)&T, g_bnT);
    cudaGetSymbolAddress((void**)&bias2, g_bias2);

    constexpr int STAGE128 = 36864 + 2 * 128 * 144;  // 73728
    constexpr int STAGE64  = 36864 + 2 * 64 * 144;   // 55296
    constexpr int SM128 = 3 * STAGE128;              // 221184
    constexpr int SM64  = 3 * STAGE64;               // 165888
    cudaFuncSetAttribute(bgemm<128, true, 1>,
                         cudaFuncAttributeMaxDynamicSharedMemorySize, SM128);
    cudaFuncSetAttribute(bgemm<64, false, 1>,
                         cudaFuncAttributeMaxDynamicSharedMemorySize, SM64);
    cudaFuncSetAttribute(bgemm<64, false, 0>,
                         cudaFuncAttributeMaxDynamicSharedMemorySize, SM64);
    cudaFuncSetAttribute(attn_kernel,
                         cudaFuncAttributeMaxDynamicSharedMemorySize, ATTN_SMEM);

    // ---- prep (2 merged launches) ----
    transposeSplitAll<<<2816, dim3(32, 8)>>>(
        W1, W3, Wq, Wv, Wo,
        W1Th, W1Tl, W3Th, W3Tl, WqTh, WqTl, WvTh, WvTl, WoTh, WoTl);
    splitAll<<<(CAT_F4 + WK_F4) / 256, 256>>>(catalog, Wk,
                                              cath, catl, Wkh, Wkl);

    // ---- FFN ----
    bgemm<128, true, 1><<<dim3(16, 16, 1), 256, SM128>>>(
        cath, catl, Dd, 0, W1Th, W1Tl, Dd, 0,
        nullptr, H1h, H1l, HIDD, 0, b1, 0, Dd, 1.f);
    bn_stats_kernel<<<HIDD / 16, 256>>>(H1h, H1l, gamma, beta, b2, S, T, bias2);
    w2prepFused<<<dim3(HIDD / 32, HIDD / 32), dim3(32, 8)>>>(
        W2, S, T, W2h, W2l, bias2);
    bgemm<128, true, 1><<<dim3(16, 16, 1), 256, SM128>>>(
        H1h, H1l, HIDD, 0, W2h, W2l, HIDD, 0,
        nullptr, H2h, H2l, HIDD, 0, bias2, 0, HIDD, 1.f);
    bgemm<64, false, 1><<<dim3(8, 16, 1), 256, SM64>>>(
        H2h, H2l, HIDD, 0, W3Th, W3Tl, HIDD, 0,
        nullptr, embh, embl, Dd, 0, b3, 0, HIDD, 1.f);

    // ---- q = emb @ Wq + bq ----
    bgemm<64, false, 1><<<dim3(8, 16, 1), 256, SM64>>>(
        embh, embl, Dd, 0, WqTh, WqTl, Dd, 0,
        nullptr, qh, ql, Dd, 0, bq, 0, Dd, 1.f);

    // ---- r[b,h,d] = (1/8) * sum_j q[b,h,j] * Wk[d, h*64+j] ----
    // K=64 -> KT=1: only stage 0 used; launch with 1-stage smem for 2 CTAs/SM
    bgemm<64, false, 0><<<dim3(8, 16, 8), 256, STAGE64>>>(
        qh, ql, Dd, DHh, Wkh, Wkl, Dd, DHh,
        r, nullptr, nullptr, Hh * Dd, Dd, nullptr, 0, DHh, 0.125f);

    // ---- single-pass flash attention (length-pruned, 256 threads) ----
    attn_kernel<<<Bb, 256, ATTN_SMEM>>>(neighbors, r, lengths, ch, cl);

    // ---- ctx = c @ Wv + bv (per head) ----
    bgemm<64, false, 1><<<dim3(1, 16, 8), 256, SM64>>>(
        ch, cl, Hh * Dd, Dd, WvTh, WvTl, Dd, (long)DHh * Dd,
        nullptr, ctxh, ctxl, Dd, DHh, bv, DHh, Dd, 1.f);

    // ---- out = ctx @ Wo + bo ----
    bgemm<64, false, 0><<<dim3(8, 16, 1), 256, SM64>>>(
        ctxh, ctxl, Dd, 0, WoTh, WoTl, Dd, 0,
        out, nullptr, nullptr, Dd, 0, bo, 0, Dd, 1.f);
}